// round 1
// baseline (speedup 1.0000x reference)
#include <cuda_runtime.h>
#include <cstdint>

#define N_TOKENS 8192
#define D_MODEL  1024
#define D_FF     4096
#define N_EXPERTS 8

#define BM 128
#define BN 128
#define BK 16
#define MAX_TILES 72   // sum ceil(c_e/128) <= 8192/128 + 8 = 72

// ---- scratch (device globals; no allocations allowed) ----
__device__ int g_top1[N_TOKENS];
__device__ int g_counts[N_EXPERTS];
__device__ int g_cursor[N_EXPERTS];
__device__ int g_offsets[N_EXPERTS + 1];
__device__ int g_order[N_TOKENS];
__device__ int g_tile_expert[MAX_TILES + 8];
__device__ int g_tile_row[MAX_TILES + 8];
__device__ int g_tile_rows[MAX_TILES + 8];
__device__ int g_ntiles;

// ---- 1. zero counters (graph replays need deterministic state) ----
__global__ void k_zero() {
    int t = threadIdx.x;
    if (t < N_EXPERTS) { g_counts[t] = 0; g_cursor[t] = 0; }
}

// ---- 2. gate: logits -> argmax (softmax is monotone, argmax(logits) == argmax(probs)) ----
__global__ void k_gate(const float* __restrict__ x,
                       const float* __restrict__ gw,
                       const float* __restrict__ gb) {
    int warp = (blockIdx.x * blockDim.x + threadIdx.x) >> 5;
    int lane = threadIdx.x & 31;
    if (warp >= N_TOKENS) return;

    const float* xr = x + (size_t)warp * D_MODEL;
    float acc[N_EXPERTS];
#pragma unroll
    for (int e = 0; e < N_EXPERTS; e++) acc[e] = 0.f;

#pragma unroll 4
    for (int i = 0; i < D_MODEL / 32; i++) {
        int d = i * 32 + lane;
        float xv = xr[d];
        const float* g = gw + d * N_EXPERTS;
#pragma unroll
        for (int e = 0; e < N_EXPERTS; e++) acc[e] += xv * g[e];
    }
#pragma unroll
    for (int e = 0; e < N_EXPERTS; e++) {
#pragma unroll
        for (int off = 16; off; off >>= 1)
            acc[e] += __shfl_xor_sync(0xffffffffu, acc[e], off);
    }
    if (lane == 0) {
        int best = 0;
        float bv = acc[0] + gb[0];
#pragma unroll
        for (int e = 1; e < N_EXPERTS; e++) {
            float v = acc[e] + gb[e];
            if (v > bv) { bv = v; best = e; }   // strict > : first max wins, matches jnp.argmax
        }
        g_top1[warp] = best;
        atomicAdd(&g_counts[best], 1);
    }
}

// ---- 3. scan + tile table (tiny; one thread) ----
__global__ void k_scan() {
    int off = 0;
    for (int e = 0; e < N_EXPERTS; e++) { g_offsets[e] = off; off += g_counts[e]; }
    g_offsets[N_EXPERTS] = off;
    int nt = 0;
    for (int e = 0; e < N_EXPERTS; e++) {
        int c = g_counts[e], base = g_offsets[e];
        for (int r = 0; r < c; r += BM) {
            g_tile_expert[nt] = e;
            g_tile_row[nt]    = base + r;
            g_tile_rows[nt]   = (c - r < BM) ? (c - r) : BM;
            nt++;
        }
    }
    g_ntiles = nt;
}

// ---- 4. scatter tokens into grouped order ----
__global__ void k_scatter() {
    int n = blockIdx.x * blockDim.x + threadIdx.x;
    if (n >= N_TOKENS) return;
    int e = g_top1[n];
    int pos = g_offsets[e] + atomicAdd(&g_cursor[e], 1);
    g_order[pos] = n;
}

// ---- 5. grouped GEMM: [nrows,1024] x [1024,4096] per expert tile ----
__global__ __launch_bounds__(256) void k_gemm(const float* __restrict__ x,
                                              const float* __restrict__ ew,
                                              const float* __restrict__ eb,
                                              float* __restrict__ out) {
    int tile = blockIdx.x;
    if (tile >= g_ntiles) return;
    int e     = g_tile_expert[tile];
    int row0  = g_tile_row[tile];
    int nrows = g_tile_rows[tile];
    int col0  = blockIdx.y * BN;

    __shared__ float As[BK][BM];
    __shared__ float Bs[BK][BN];
    __shared__ int   s_tok[BM];

    int tid = threadIdx.x;
    for (int m = tid; m < BM; m += 256)
        s_tok[m] = (m < nrows) ? g_order[row0 + m] : -1;
    __syncthreads();

    const float* W = ew + (size_t)e * D_MODEL * D_FF;
    int tx = tid & 15;       // 16 cols of threads -> 8 output cols each
    int ty = tid >> 4;       // 16 rows of threads -> 8 output rows each

    float c[8][8];
#pragma unroll
    for (int i = 0; i < 8; i++)
#pragma unroll
        for (int j = 0; j < 8; j++) c[i][j] = 0.f;

    for (int k0 = 0; k0 < D_MODEL; k0 += BK) {
        // A: 128 rows x 16 k  (512 float4 loads, 2 per thread)
#pragma unroll
        for (int l = 0; l < 2; l++) {
            int idx = tid + l * 256;
            int m  = idx >> 2;
            int kq = idx & 3;
            int tok = s_tok[m];
            float4 v = make_float4(0.f, 0.f, 0.f, 0.f);
            if (tok >= 0)
                v = *(const float4*)(x + (size_t)tok * D_MODEL + k0 + kq * 4);
            As[kq * 4 + 0][m] = v.x;
            As[kq * 4 + 1][m] = v.y;
            As[kq * 4 + 2][m] = v.z;
            As[kq * 4 + 3][m] = v.w;
        }
        // B: 16 k x 128 n (512 float4 loads, 2 per thread, fully coalesced)
#pragma unroll
        for (int l = 0; l < 2; l++) {
            int idx = tid + l * 256;
            int kk = idx >> 5;
            int nq = idx & 31;
            float4 v = *(const float4*)(W + (size_t)(k0 + kk) * D_FF + col0 + nq * 4);
            *(float4*)&Bs[kk][nq * 4] = v;
        }
        __syncthreads();

#pragma unroll
        for (int kk = 0; kk < BK; kk++) {
            float a[8], b[8];
            *(float4*)(a)     = *(const float4*)&As[kk][ty * 8];
            *(float4*)(a + 4) = *(const float4*)&As[kk][ty * 8 + 4];
            *(float4*)(b)     = *(const float4*)&Bs[kk][tx * 8];
            *(float4*)(b + 4) = *(const float4*)&Bs[kk][tx * 8 + 4];
#pragma unroll
            for (int i = 0; i < 8; i++)
#pragma unroll
                for (int j = 0; j < 8; j++)
                    c[i][j] += a[i] * b[j];
        }
        __syncthreads();
    }

    // epilogue: add bias, scatter rows back to original token positions
    float bb[8];
    *(float4*)(bb)     = *(const float4*)(eb + (size_t)e * D_FF + col0 + tx * 8);
    *(float4*)(bb + 4) = *(const float4*)(eb + (size_t)e * D_FF + col0 + tx * 8 + 4);

#pragma unroll
    for (int i = 0; i < 8; i++) {
        int m = ty * 8 + i;
        int tok = s_tok[m];
        if (tok < 0) continue;
        float* o = out + (size_t)tok * D_FF + col0 + tx * 8;
        float4 r0, r1;
        r0.x = c[i][0] + bb[0]; r0.y = c[i][1] + bb[1];
        r0.z = c[i][2] + bb[2]; r0.w = c[i][3] + bb[3];
        r1.x = c[i][4] + bb[4]; r1.y = c[i][5] + bb[5];
        r1.z = c[i][6] + bb[6]; r1.w = c[i][7] + bb[7];
        *(float4*)(o)     = r0;
        *(float4*)(o + 4) = r1;
    }
}

extern "C" void kernel_launch(void* const* d_in, const int* in_sizes, int n_in,
                              void* d_out, int out_size) {
    const float* x   = (const float*)d_in[0];   // [8192, 1024]
    const float* gw  = (const float*)d_in[1];   // [1024, 8]
    const float* gb  = (const float*)d_in[2];   // [8]
    const float* ew  = (const float*)d_in[3];   // [8, 1024, 4096]
    const float* eb  = (const float*)d_in[4];   // [8, 4096]
    float* out = (float*)d_out;                 // [8192, 4096]

    k_zero<<<1, 32>>>();
    k_gate<<<N_TOKENS / 8, 256>>>(x, gw, gb);   // 8 warps/block, 1 warp/token
    k_scan<<<1, 1>>>();
    k_scatter<<<N_TOKENS / 256, 256>>>();
    dim3 grid(MAX_TILES, D_FF / BN);
    k_gemm<<<grid, 256>>>(x, ew, eb, out);
}

// round 3
// speedup vs baseline: 2.5375x; 2.5375x over previous
#include <cuda_runtime.h>
#include <cuda_bf16.h>
#include <cstdint>

#define N_TOKENS 8192
#define D_MODEL  1024
#define D_FF     4096
#define N_EXPERTS 8

#define BM 128
#define BN 256
#define BK 32
#define NKSTAGE (D_MODEL / BK)        // 32
#define PIPE 4
#define MAX_TILES 72
#define PAD_ROWS (N_TOKENS + N_EXPERTS * BM)   // 9216

// ---------------- scratch ----------------
__device__ int g_top1[N_TOKENS];
__device__ int g_counts[N_EXPERTS];
__device__ int g_cursor[N_EXPERTS];
__device__ int g_offsets[N_EXPERTS];           // padded base per expert
__device__ int g_order[PAD_ROWS];              // -1 = pad row
__device__ int g_tile_expert[MAX_TILES + 8];
__device__ int g_tile_row[MAX_TILES + 8];
__device__ int g_ntiles;

__device__ __nv_bfloat16 g_xh[(size_t)PAD_ROWS * D_MODEL];   // grouped+padded
__device__ __nv_bfloat16 g_xl[(size_t)PAD_ROWS * D_MODEL];
__device__ __nv_bfloat16 g_wth[(size_t)N_EXPERTS * D_FF * D_MODEL];  // W^T hi
__device__ __nv_bfloat16 g_wtl[(size_t)N_EXPERTS * D_FF * D_MODEL];  // W^T lo

// ---------------- helpers ----------------
__device__ __forceinline__ uint32_t smem_u32(const void* p) {
    uint32_t a;
    asm("{ .reg .u64 t; cvta.to.shared.u64 t, %1; cvt.u32.u64 %0, t; }" : "=r"(a) : "l"(p));
    return a;
}
__device__ __forceinline__ void cp16(uint32_t dst, const void* src) {
    asm volatile("cp.async.cg.shared.global [%0], [%1], 16;\n" :: "r"(dst), "l"(src));
}
__device__ __forceinline__ void cp_commit() { asm volatile("cp.async.commit_group;\n" ::: "memory"); }
template <int N> __device__ __forceinline__ void cp_wait() {
    asm volatile("cp.async.wait_group %0;\n" :: "n"(N) : "memory");
}
__device__ __forceinline__ void ldsm4(uint32_t r[4], uint32_t addr) {
    asm volatile("ldmatrix.sync.aligned.m8n8.x4.shared.b16 {%0,%1,%2,%3}, [%4];"
                 : "=r"(r[0]), "=r"(r[1]), "=r"(r[2]), "=r"(r[3]) : "r"(addr));
}
#define MMA(d, a, b0, b1)                                                          \
    asm volatile("mma.sync.aligned.m16n8k16.row.col.f32.bf16.bf16.f32 "            \
                 "{%0,%1,%2,%3},{%4,%5,%6,%7},{%8,%9},{%0,%1,%2,%3};"              \
                 : "+f"((d)[0]), "+f"((d)[1]), "+f"((d)[2]), "+f"((d)[3])          \
                 : "r"((a)[0]), "r"((a)[1]), "r"((a)[2]), "r"((a)[3]),             \
                   "r"(b0), "r"(b1))

// smem tile: rows of 32 bf16 (64B) as 4 x 16B chunks, chunk ^= (row>>1)&3
__device__ __forceinline__ uint32_t swz(int row, int c) {
    return (uint32_t)(row * 64 + ((c ^ ((row >> 1) & 3)) << 4));
}

#define STAGE_BYTES 49152          // A(hi,lo) 16K + B(hi,lo) 32K
#define A_LO 8192
#define B_OFF 16384
#define B_LO 16384                 // relative to B_OFF
#define SMEM_TOTAL (PIPE * STAGE_BYTES)   // 196608

// ---------------- gate path ----------------
__global__ void k_init() {
    int i = blockIdx.x * blockDim.x + threadIdx.x;
    if (i < N_EXPERTS) { g_counts[i] = 0; g_cursor[i] = 0; }
    if (i < PAD_ROWS) g_order[i] = -1;
}

__global__ void k_gate(const float* __restrict__ x, const float* __restrict__ gw,
                       const float* __restrict__ gb) {
    int warp = (blockIdx.x * blockDim.x + threadIdx.x) >> 5;
    int lane = threadIdx.x & 31;
    if (warp >= N_TOKENS) return;
    const float* xr = x + (size_t)warp * D_MODEL;
    float acc[N_EXPERTS];
#pragma unroll
    for (int e = 0; e < N_EXPERTS; e++) acc[e] = 0.f;
#pragma unroll 4
    for (int i = 0; i < D_MODEL / 32; i++) {
        int d = i * 32 + lane;
        float xv = xr[d];
        const float* g = gw + d * N_EXPERTS;
#pragma unroll
        for (int e = 0; e < N_EXPERTS; e++) acc[e] += xv * g[e];
    }
#pragma unroll
    for (int e = 0; e < N_EXPERTS; e++)
#pragma unroll
        for (int off = 16; off; off >>= 1)
            acc[e] += __shfl_xor_sync(0xffffffffu, acc[e], off);
    if (lane == 0) {
        int best = 0;
        float bv = acc[0] + gb[0];
#pragma unroll
        for (int e = 1; e < N_EXPERTS; e++) {
            float v = acc[e] + gb[e];
            if (v > bv) { bv = v; best = e; }   // first max wins == jnp.argmax
        }
        g_top1[warp] = best;
        atomicAdd(&g_counts[best], 1);
    }
}

__global__ void k_scan() {
    int base = 0, nt = 0;
    for (int e = 0; e < N_EXPERTS; e++) {
        g_offsets[e] = base;
        int c = g_counts[e];
        int t = (c + BM - 1) / BM;
        for (int r = 0; r < t; r++) {
            g_tile_expert[nt] = e;
            g_tile_row[nt] = base + r * BM;
            nt++;
        }
        base += t * BM;              // padded region
    }
    g_ntiles = nt;
}

__global__ void k_scatter() {
    int n = blockIdx.x * blockDim.x + threadIdx.x;
    if (n >= N_TOKENS) return;
    int e = g_top1[n];
    int pos = g_offsets[e] + atomicAdd(&g_cursor[e], 1);
    g_order[pos] = n;
}

// ---------------- splits ----------------
// gather token row into grouped/padded position + bf16 hi/lo split
__global__ void k_split_x(const float* __restrict__ x) {
    int pos = blockIdx.x;
    int tok = g_order[pos];
    int c0 = threadIdx.x * 4;
    __nv_bfloat16 h[4], l[4];
    if (tok >= 0) {
        float4 v = *(const float4*)(x + (size_t)tok * D_MODEL + c0);
        float f[4] = {v.x, v.y, v.z, v.w};
#pragma unroll
        for (int j = 0; j < 4; j++) {
            h[j] = __float2bfloat16(f[j]);
            l[j] = __float2bfloat16(f[j] - __bfloat162float(h[j]));
        }
    } else {
#pragma unroll
        for (int j = 0; j < 4; j++) { h[j] = __float2bfloat16(0.f); l[j] = h[j]; }
    }
    size_t o = (size_t)pos * D_MODEL + c0;
    *(uint2*)(g_xh + o) = *(uint2*)h;
    *(uint2*)(g_xl + o) = *(uint2*)l;
}

// transpose W[e][d][f] -> W^T[e][f][d] + split
__global__ void k_split_wt(const float* __restrict__ ew) {
    __shared__ float ts[32][33];
    int e = blockIdx.z;
    int f0 = blockIdx.x * 32;
    int d0 = blockIdx.y * 32;
    int c = threadIdx.x & 31;
    int r0 = threadIdx.x >> 5;
    const float* W = ew + (size_t)e * D_MODEL * D_FF;
#pragma unroll
    for (int r = r0; r < 32; r += 8)
        ts[r][c] = W[(size_t)(d0 + r) * D_FF + f0 + c];
    __syncthreads();
#pragma unroll
    for (int r = r0; r < 32; r += 8) {
        float v = ts[c][r];
        __nv_bfloat16 h = __float2bfloat16(v);
        __nv_bfloat16 l = __float2bfloat16(v - __bfloat162float(h));
        size_t o = ((size_t)e * D_FF + f0 + r) * D_MODEL + d0 + c;
        g_wth[o] = h;
        g_wtl[o] = l;
    }
}

// ---------------- HMMA grouped GEMM ----------------
__device__ __forceinline__ void issue_stage(int tid, uint32_t sb, int stage,
                                            int row0, size_t wbase, int k0) {
    uint32_t base = sb + (stage % PIPE) * STAGE_BYTES;
    // A: 128 rows x 4 chunks x 2 terms = 1024 cp16
#pragma unroll
    for (int i = 0; i < 2; i++) {
        int idx = tid + i * 512;
        int term = idx >> 9, rem = idx & 511;
        int row = rem >> 2, c = rem & 3;
        const __nv_bfloat16* src =
            (term ? g_xl : g_xh) + (size_t)(row0 + row) * D_MODEL + k0 + c * 8;
        cp16(base + term * A_LO + swz(row, c), src);
    }
    // B: 256 rows x 4 chunks x 2 terms = 2048 cp16
#pragma unroll
    for (int i = 0; i < 4; i++) {
        int idx = tid + i * 512;
        int term = idx >> 10, rem = idx & 1023;
        int row = rem >> 2, c = rem & 3;
        const __nv_bfloat16* src =
            (term ? g_wtl : g_wth) + wbase + (size_t)row * D_MODEL + k0 + c * 8;
        cp16(base + B_OFF + term * B_LO + swz(row, c), src);
    }
    cp_commit();
}

__global__ void __launch_bounds__(512, 1)
k_gemm(const float* __restrict__ eb, float* __restrict__ out) {
    int tile = blockIdx.x;
    if (tile >= g_ntiles) return;
    int e = g_tile_expert[tile];
    int row0 = g_tile_row[tile];
    int col0 = blockIdx.y * BN;

    extern __shared__ char smem[];
    __shared__ int s_tok[BM];
    uint32_t sb = smem_u32(smem);
    int tid = threadIdx.x;
    int lane = tid & 31;
    int wid = tid >> 5;
    int wm = wid & 3;        // 4 M groups (32 rows each)
    int wn = wid >> 2;       // 4 N groups (64 cols each)

    for (int m = tid; m < BM; m += 512) s_tok[m] = g_order[row0 + m];

    size_t wbase = ((size_t)e * D_FF + col0) * D_MODEL;

    float acc[2][8][4];
#pragma unroll
    for (int a = 0; a < 2; a++)
#pragma unroll
        for (int b = 0; b < 8; b++)
#pragma unroll
            for (int c = 0; c < 4; c++) acc[a][b][c] = 0.f;

#pragma unroll
    for (int p = 0; p < PIPE - 1; p++) issue_stage(tid, sb, p, row0, wbase, p * BK);

    // precompute per-lane ldmatrix offsets (within a stage buffer)
    int a_row = wm * 32 + (lane & 15);
    int b_row = wn * 64 + (lane & 7) + ((lane >> 4) << 3);
    int a_cbit = (lane >> 4) & 1;
    int b_cbit = (lane >> 3) & 1;

    for (int s = 0; s < NKSTAGE; s++) {
        cp_wait<PIPE - 2>();
        __syncthreads();
        if (s + PIPE - 1 < NKSTAGE)
            issue_stage(tid, sb, s + PIPE - 1, row0, wbase, (s + PIPE - 1) * BK);
        else
            cp_commit();   // keep wait_group accounting aligned

        uint32_t abase = sb + (s % PIPE) * STAGE_BYTES;
        uint32_t bbase = abase + B_OFF;

#pragma unroll
        for (int ks = 0; ks < 2; ks++) {
            uint32_t ah[2][4], al[2][4];
#pragma unroll
            for (int mf = 0; mf < 2; mf++) {
                int row = a_row + mf * 16;
                uint32_t addr = abase + swz(row, ks * 2 + a_cbit);
                ldsm4(ah[mf], addr);
                ldsm4(al[mf], addr + A_LO);
            }
#pragma unroll
            for (int np = 0; np < 4; np++) {
                int row = b_row + np * 16;
                uint32_t addr = bbase + swz(row, ks * 2 + b_cbit);
                uint32_t bh[4], bl[4];
                ldsm4(bh, addr);
                ldsm4(bl, addr + B_LO);
#pragma unroll
                for (int sub = 0; sub < 2; sub++) {
                    MMA(acc[0][np * 2 + sub], ah[0], bh[sub * 2], bh[sub * 2 + 1]);
                    MMA(acc[1][np * 2 + sub], ah[1], bh[sub * 2], bh[sub * 2 + 1]);
                    MMA(acc[0][np * 2 + sub], ah[0], bl[sub * 2], bl[sub * 2 + 1]);
                    MMA(acc[1][np * 2 + sub], ah[1], bl[sub * 2], bl[sub * 2 + 1]);
                    MMA(acc[0][np * 2 + sub], al[0], bh[sub * 2], bh[sub * 2 + 1]);
                    MMA(acc[1][np * 2 + sub], al[1], bh[sub * 2], bh[sub * 2 + 1]);
                }
            }
        }
    }
    __syncthreads();

    // epilogue: C frag rows -> tokens, add bias
    const float* bias = eb + (size_t)e * D_FF + col0 + wn * 64;
#pragma unroll
    for (int mf = 0; mf < 2; mf++) {
        int r_lo = wm * 32 + mf * 16 + (lane >> 2);
        int t_lo = s_tok[r_lo];
        int t_hi = s_tok[r_lo + 8];
#pragma unroll
        for (int nf = 0; nf < 8; nf++) {
            int cb = nf * 8 + (lane & 3) * 2;
            float b0 = bias[cb], b1 = bias[cb + 1];
            float* o0 = out + (size_t)t_lo * D_FF + col0 + wn * 64 + cb;
            float* o1 = out + (size_t)t_hi * D_FF + col0 + wn * 64 + cb;
            if (t_lo >= 0) {
                float2 v = {acc[mf][nf][0] + b0, acc[mf][nf][1] + b1};
                *(float2*)o0 = v;
            }
            if (t_hi >= 0) {
                float2 v = {acc[mf][nf][2] + b0, acc[mf][nf][3] + b1};
                *(float2*)o1 = v;
            }
        }
    }
}

extern "C" void kernel_launch(void* const* d_in, const int* in_sizes, int n_in,
                              void* d_out, int out_size) {
    const float* x  = (const float*)d_in[0];
    const float* gw = (const float*)d_in[1];
    const float* gb = (const float*)d_in[2];
    const float* ew = (const float*)d_in[3];
    const float* eb = (const float*)d_in[4];
    float* out = (float*)d_out;

    cudaFuncSetAttribute(k_gemm, cudaFuncAttributeMaxDynamicSharedMemorySize, SMEM_TOTAL);

    k_init<<<(PAD_ROWS + 255) / 256, 256>>>();
    k_gate<<<N_TOKENS / 8, 256>>>(x, gw, gb);
    k_scan<<<1, 1>>>();
    k_scatter<<<N_TOKENS / 256, 256>>>();
    k_split_x<<<PAD_ROWS, 256>>>(x);
    {
        dim3 g(D_FF / 32, D_MODEL / 32, N_EXPERTS);
        k_split_wt<<<g, 256>>>(ew);
    }
    {
        dim3 g(MAX_TILES, D_FF / BN);
        k_gemm<<<g, 512, SMEM_TOTAL>>>(eb, out);
    }
}